// round 9
// baseline (speedup 1.0000x reference)
#include <cuda_runtime.h>
#include <cuda_bf16.h>
#include <math_constants.h>

#define BATCH 1024
#define SEQL  1024
#define NCAT  20
#define NNUM  10
#define EDIM  32
#define ADIM  128
#define HDIM  256
#define TOPK  30
#define ROWS  8

// scratch: fused feature vectors [B, 4E=128]
__device__ float g_fused[BATCH * 128];

// ---------------------------------------------------------------------------
// Phase 1: per-row attention + feature fusion. One CTA per batch row.
// ---------------------------------------------------------------------------
__global__ void __launch_bounds__(256) k_attn(
    const int* __restrict__ cats, const float* __restrict__ nums,
    const int* __restrict__ seqs, const int* __restrict__ tgt_ids,
    const float* __restrict__ cat_emb, const float* __restrict__ seq_emb,
    const float* __restrict__ Wnum, const float* __restrict__ bnum,
    const float* __restrict__ Wq,  const float* __restrict__ Wk,
    const float* __restrict__ Wv,  const float* __restrict__ Wo,
    const float* __restrict__ bo,  const float* __restrict__ Wpool,
    const float* __restrict__ bpool)
{
    __shared__ float s_tgt[EDIM];
    __shared__ float s_q[ADIM];
    __shared__ float s_qk[EDIM];
    __shared__ float s_scores[SEQL];
    __shared__ float s_cat[NCAT * EDIM];
    __shared__ float s_red[256];
    __shared__ float s_topw[TOPK];
    __shared__ int   s_toptok[TOPK];
    __shared__ float s_ctx[EDIM];
    __shared__ float s_tmp[ADIM];

    const int b    = blockIdx.x;
    const int t    = threadIdx.x;
    const int lane = t & 31;
    const int warp = t >> 5;

    // target embedding + categorical embeddings
    if (t < EDIM) s_tgt[t] = cat_emb[(long)tgt_ids[b] * EDIM + t];
    for (int i = t; i < NCAT * EDIM; i += 256) {
        int c = i >> 5, e = i & 31;
        s_cat[i] = cat_emb[(long)cats[b * NCAT + c] * EDIM + e];
    }
    __syncthreads();

    // q = tgt_e @ Wq   [A]
    if (t < ADIM) {
        float acc = 0.f;
        #pragma unroll
        for (int e = 0; e < EDIM; e++) acc += s_tgt[e] * Wq[e * ADIM + t];
        s_q[t] = acc;
    }
    __syncthreads();

    // qk = Wk @ q      [E]   (so scores are 32-wide dots with seq_emb rows)
    if (t < EDIM) {
        float acc = 0.f;
        for (int a = 0; a < ADIM; a++) acc += Wk[t * ADIM + a] * s_q[a];
        s_qk[t] = acc;
    }
    __syncthreads();

    // scores[l] = (qk . seq_emb[seqs[b,l]]) / sqrt(A)
    // 8 lanes per token row (float4 each), 4 tokens per warp concurrently,
    // 16 tokens per iteration -> 4 independent LDG.128 in flight per lane.
    const float scale = rsqrtf((float)ADIM);
    const int sub = lane & 7;       // position within token row
    const int tg  = lane >> 3;      // which of 4 concurrent tokens
    const float4 qv4 = *(const float4*)&s_qk[sub * 4];
    const int* srow = seqs + (long)b * SEQL;
    for (int p = warp * 128; p < warp * 128 + 128; p += 16) {
        int tokA = srow[p + tg];
        int tokB = srow[p + 4 + tg];
        int tokC = srow[p + 8 + tg];
        int tokD = srow[p + 12 + tg];
        float4 ea = *(const float4*)(seq_emb + (long)tokA * EDIM + sub * 4);
        float4 eb = *(const float4*)(seq_emb + (long)tokB * EDIM + sub * 4);
        float4 ec = *(const float4*)(seq_emb + (long)tokC * EDIM + sub * 4);
        float4 ed = *(const float4*)(seq_emb + (long)tokD * EDIM + sub * 4);
        float va = ea.x * qv4.x + ea.y * qv4.y + ea.z * qv4.z + ea.w * qv4.w;
        float vb = eb.x * qv4.x + eb.y * qv4.y + eb.z * qv4.z + eb.w * qv4.w;
        float vc = ec.x * qv4.x + ec.y * qv4.y + ec.z * qv4.z + ec.w * qv4.w;
        float vd = ed.x * qv4.x + ed.y * qv4.y + ed.z * qv4.z + ed.w * qv4.w;
        #pragma unroll
        for (int o = 4; o > 0; o >>= 1) {
            va += __shfl_xor_sync(0xffffffffu, va, o);
            vb += __shfl_xor_sync(0xffffffffu, vb, o);
            vc += __shfl_xor_sync(0xffffffffu, vc, o);
            vd += __shfl_xor_sync(0xffffffffu, vd, o);
        }
        if (sub == 0) {
            s_scores[p + tg]      = va * scale;
            s_scores[p + 4 + tg]  = vb * scale;
            s_scores[p + 8 + tg]  = vc * scale;
            s_scores[p + 12 + tg] = vd * scale;
        }
    }
    __syncthreads();

    // ---- top-30 + softmax: single warp, register-resident, no block barriers
    if (warp == 0) {
        // lane holds scores at indices r*32+lane, r = 0..31
        float sc[32];
        #pragma unroll
        for (int r = 0; r < 32; r++) sc[r] = s_scores[r * 32 + lane];

        float myval = -CUDART_INF_F;   // lane k keeps k-th top value
        int   myidx = 0;               // and its sequence position

        for (int k = 0; k < TOPK; k++) {
            // local argmax over 32 regs; strict > keeps lowest in-lane index
            float bv = sc[0]; int br = 0;
            #pragma unroll
            for (int r = 1; r < 32; r++)
                if (sc[r] > bv) { bv = sc[r]; br = r; }
            int bi = br * 32 + lane;
            // cross-lane argmax, tie -> lower index
            #pragma unroll
            for (int o = 16; o > 0; o >>= 1) {
                float ov = __shfl_xor_sync(0xffffffffu, bv, o);
                int   oi = __shfl_xor_sync(0xffffffffu, bi, o);
                if (ov > bv || (ov == bv && oi < bi)) { bv = ov; bi = oi; }
            }
            // all lanes agree on (bv, bi): record in lane k
            if (lane == k) { myval = bv; myidx = bi; }
            // knock out the winner WITHOUT dynamic indexing (keeps sc[] in
            // registers: a runtime-indexed store would demote it to local mem)
            const int kr = bi >> 5;       // register slot of winner
            const int kl = bi & 31;       // owning lane of winner
            #pragma unroll
            for (int r = 0; r < 32; r++)
                sc[r] = (r == kr && lane == kl) ? -CUDART_INF_F : sc[r];
        }

        // softmax over the 30 values (lanes 0..29)
        float m = myval;
        #pragma unroll
        for (int o = 16; o > 0; o >>= 1) m = fmaxf(m, __shfl_xor_sync(0xffffffffu, m, o));
        float ev = (lane < TOPK) ? expf(myval - m) : 0.f;
        float s = ev;
        #pragma unroll
        for (int o = 16; o > 0; o >>= 1) s += __shfl_xor_sync(0xffffffffu, s, o);
        if (lane < TOPK) {
            s_topw[lane]   = ev / s;
            s_toptok[lane] = srow[myidx];   // 30 parallel LDGs, not serial
        }
    }
    __syncthreads();

    // ctx[e] = sum_k w_k * seq_emb[tok_k][e]   (weights folded into E-space)
    if (t < EDIM) {
        float acc = 0.f;
        #pragma unroll
        for (int k = 0; k < TOPK; k++)
            acc += s_topw[k] * seq_emb[(long)s_toptok[k] * EDIM + t];
        s_ctx[t] = acc;
    }
    __syncthreads();

    // tmp = ctx @ Wv  [A]
    if (t < ADIM) {
        float acc = 0.f;
        #pragma unroll
        for (int e = 0; e < EDIM; e++) acc += s_ctx[e] * Wv[e * ADIM + t];
        s_tmp[t] = acc;
    }
    // cat_pool partials: 8 warps x 80-slice each, output dim j = lane
    {
        float cp = 0.f;
        const int j = lane;
        const int i0 = warp * 80;
        for (int i = i0; i < i0 + 80; i++)
            cp += s_cat[i] * Wpool[i * EDIM + j];
        s_red[t] = cp;
    }
    __syncthreads();

    if (t < EDIM) {
        // interest = tmp @ Wo + bo
        float inter = bo[t];
        for (int a = 0; a < ADIM; a++) inter += s_tmp[a] * Wo[a * EDIM + t];
        // cat_pool = sum of 8 partials + bias
        float cp = bpool[t];
        #pragma unroll
        for (int p = 0; p < 8; p++) cp += s_red[p * 32 + t];
        // num_e
        float ne = bnum[t];
        #pragma unroll
        for (int i = 0; i < NNUM; i++) ne += nums[b * NNUM + i] * Wnum[i * EDIM + t];

        float* fo = g_fused + (long)b * 128;
        fo[t]      = s_tgt[t];
        fo[32 + t] = inter;
        fo[64 + t] = cp;
        fo[96 + t] = ne;
    }
}

// ---------------------------------------------------------------------------
// Phase 2: MLP + 2x QNN + head. 8 batch rows per CTA (amortize weight reads).
// Shared operands read via float4 (LDS.128) to cut issue slots ~25%.
// ---------------------------------------------------------------------------
__global__ void __launch_bounds__(256) k_mlp(
    const float* __restrict__ Wmlp, const float* __restrict__ bmlp,
    const float* __restrict__ W1a, const float* __restrict__ b1a,
    const float* __restrict__ W2a, const float* __restrict__ b2a,
    const float* __restrict__ Wpa, const float* __restrict__ bpa,
    const float* __restrict__ W1b, const float* __restrict__ b1b,
    const float* __restrict__ W2b, const float* __restrict__ b2b,
    const float* __restrict__ Wpb, const float* __restrict__ bpb,
    const float* __restrict__ Wout, const float* __restrict__ bout,
    float* __restrict__ out)
{
    __shared__ float s_f[ROWS][128];
    __shared__ float s_h[ROWS][HDIM];
    __shared__ float s_qd[ROWS][HDIM];

    const int t  = threadIdx.x;
    const int b0 = blockIdx.x * ROWS;
    const int j  = t;

    for (int i = t; i < ROWS * 128; i += 256)
        ((float*)s_f)[i] = g_fused[(long)b0 * 128 + i];
    __syncthreads();

    // h = relu(fused @ Wmlp + bmlp)
    float acc[ROWS];
    {
        float bm = bmlp[j];
        #pragma unroll
        for (int r = 0; r < ROWS; r++) acc[r] = bm;
        for (int i = 0; i < 128; i += 4) {
            float4 w4;
            w4.x = Wmlp[(i + 0) * HDIM + j];
            w4.y = Wmlp[(i + 1) * HDIM + j];
            w4.z = Wmlp[(i + 2) * HDIM + j];
            w4.w = Wmlp[(i + 3) * HDIM + j];
            #pragma unroll
            for (int r = 0; r < ROWS; r++) {
                float4 f4 = *(const float4*)&s_f[r][i];
                acc[r] += f4.x * w4.x + f4.y * w4.y + f4.z * w4.z + f4.w * w4.w;
            }
        }
        #pragma unroll
        for (int r = 0; r < ROWS; r++) s_h[r][j] = fmaxf(acc[r], 0.f);
    }
    __syncthreads();

    // two QNN blocks
    #pragma unroll 1
    for (int blk = 0; blk < 2; blk++) {
        const float* W1 = blk ? W1b : W1a;
        const float* B1 = blk ? b1b : b1a;
        const float* W2 = blk ? W2b : W2a;
        const float* B2 = blk ? b2b : b2a;
        const float* Wp = blk ? Wpb : Wpa;
        const float* Bp = blk ? bpb : bpa;

        float t1[ROWS], t2[ROWS];
        float bb1 = B1[j], bb2 = B2[j];
        #pragma unroll
        for (int r = 0; r < ROWS; r++) { t1[r] = bb1; t2[r] = bb2; }
        for (int i = 0; i < HDIM; i += 4) {
            float4 w14, w24;
            w14.x = W1[(i + 0) * HDIM + j]; w24.x = W2[(i + 0) * HDIM + j];
            w14.y = W1[(i + 1) * HDIM + j]; w24.y = W2[(i + 1) * HDIM + j];
            w14.z = W1[(i + 2) * HDIM + j]; w24.z = W2[(i + 2) * HDIM + j];
            w14.w = W1[(i + 3) * HDIM + j]; w24.w = W2[(i + 3) * HDIM + j];
            #pragma unroll
            for (int r = 0; r < ROWS; r++) {
                float4 h4 = *(const float4*)&s_h[r][i];
                t1[r] += h4.x * w14.x + h4.y * w14.y + h4.z * w14.z + h4.w * w14.w;
                t2[r] += h4.x * w24.x + h4.y * w24.y + h4.z * w24.z + h4.w * w24.w;
            }
        }
        #pragma unroll
        for (int r = 0; r < ROWS; r++) s_qd[r][j] = t1[r] * t2[r];
        __syncthreads();

        float bp_ = Bp[j];
        #pragma unroll
        for (int r = 0; r < ROWS; r++) acc[r] = bp_;
        for (int i = 0; i < HDIM; i += 4) {
            float4 wp4;
            wp4.x = Wp[(i + 0) * HDIM + j];
            wp4.y = Wp[(i + 1) * HDIM + j];
            wp4.z = Wp[(i + 2) * HDIM + j];
            wp4.w = Wp[(i + 3) * HDIM + j];
            #pragma unroll
            for (int r = 0; r < ROWS; r++) {
                float4 q4 = *(const float4*)&s_qd[r][i];
                acc[r] += q4.x * wp4.x + q4.y * wp4.y + q4.z * wp4.z + q4.w * wp4.w;
            }
        }
        #pragma unroll
        for (int r = 0; r < ROWS; r++) s_h[r][j] += acc[r];   // residual
        __syncthreads();
    }

    // head: out[b] = h . Wout + bout   (one warp per row)
    {
        const int r = t >> 5, lane = t & 31;
        float sum = 0.f;
        for (int jj = lane; jj < HDIM; jj += 32)
            sum += s_h[r][jj] * Wout[jj];
        #pragma unroll
        for (int o = 16; o > 0; o >>= 1)
            sum += __shfl_xor_sync(0xffffffffu, sum, o);
        if (lane == 0) out[b0 + r] = sum + bout[0];
    }
}

extern "C" void kernel_launch(void* const* d_in, const int* in_sizes, int n_in,
                              void* d_out, int out_size)
{
    const int*   cats    = (const int*)d_in[0];
    const float* nums    = (const float*)d_in[1];
    const int*   seqs    = (const int*)d_in[2];
    const int*   tgt_ids = (const int*)d_in[3];
    const float* cat_emb = (const float*)d_in[4];
    const float* seq_emb = (const float*)d_in[5];
    const float* Wnum    = (const float*)d_in[6];
    const float* bnum    = (const float*)d_in[7];
    const float* Wq      = (const float*)d_in[8];
    const float* Wk      = (const float*)d_in[9];
    const float* Wv      = (const float*)d_in[10];
    const float* Wo      = (const float*)d_in[11];
    const float* bo      = (const float*)d_in[12];
    const float* Wpool   = (const float*)d_in[13];
    const float* bpool   = (const float*)d_in[14];
    const float* Wmlp    = (const float*)d_in[15];
    const float* bmlp    = (const float*)d_in[16];
    const float* q1_W1   = (const float*)d_in[17];
    const float* q1_b1   = (const float*)d_in[18];
    const float* q1_W2   = (const float*)d_in[19];
    const float* q1_b2   = (const float*)d_in[20];
    const float* q1_Wp   = (const float*)d_in[21];
    const float* q1_bp   = (const float*)d_in[22];
    const float* q2_W1   = (const float*)d_in[23];
    const float* q2_b1   = (const float*)d_in[24];
    const float* q2_W2   = (const float*)d_in[25];
    const float* q2_b2   = (const float*)d_in[26];
    const float* q2_Wp   = (const float*)d_in[27];
    const float* q2_bp   = (const float*)d_in[28];
    const float* Wout    = (const float*)d_in[29];
    const float* bout    = (const float*)d_in[30];
    float* out = (float*)d_out;

    k_attn<<<BATCH, 256>>>(cats, nums, seqs, tgt_ids, cat_emb, seq_emb,
                           Wnum, bnum, Wq, Wk, Wv, Wo, bo, Wpool, bpool);
    k_mlp<<<BATCH / ROWS, 256>>>(Wmlp, bmlp,
                                 q1_W1, q1_b1, q1_W2, q1_b2, q1_Wp, q1_bp,
                                 q2_W1, q2_b1, q2_W2, q2_b2, q2_Wp, q2_bp,
                                 Wout, bout, out);
}

// round 16
// speedup vs baseline: 1.2976x; 1.2976x over previous
#include <cuda_runtime.h>
#include <cuda_bf16.h>
#include <math_constants.h>

#define BATCH 1024
#define SEQL  1024
#define NCAT  20
#define NNUM  10
#define EDIM  32
#define ADIM  128
#define HDIM  256
#define TOPK  30
#define ROWS  8

// scratch: fused feature vectors [B, 4E=128]
__device__ float g_fused[BATCH * 128];

// ---------------------------------------------------------------------------
// Phase 1: per-row attention + feature fusion. One CTA per batch row.
// ---------------------------------------------------------------------------
__global__ void __launch_bounds__(256) k_attn(
    const int* __restrict__ cats, const float* __restrict__ nums,
    const int* __restrict__ seqs, const int* __restrict__ tgt_ids,
    const float* __restrict__ cat_emb, const float* __restrict__ seq_emb,
    const float* __restrict__ Wnum, const float* __restrict__ bnum,
    const float* __restrict__ Wq,  const float* __restrict__ Wk,
    const float* __restrict__ Wv,  const float* __restrict__ Wo,
    const float* __restrict__ bo,  const float* __restrict__ Wpool,
    const float* __restrict__ bpool)
{
    __shared__ float s_tgt[EDIM];
    __shared__ float s_q[ADIM];
    __shared__ float s_qk[EDIM];
    __shared__ float s_scores[SEQL];
    __shared__ float s_cat[NCAT * EDIM];
    __shared__ float s_red[256];
    __shared__ float s_topw[TOPK];
    __shared__ int   s_toptok[TOPK];
    __shared__ float s_ctx[EDIM];
    __shared__ float s_tmp[ADIM];

    const int b    = blockIdx.x;
    const int t    = threadIdx.x;
    const int lane = t & 31;
    const int warp = t >> 5;

    if (t < EDIM) s_tgt[t] = cat_emb[(long)tgt_ids[b] * EDIM + t];
    for (int i = t; i < NCAT * EDIM; i += 256) {
        int c = i >> 5, e = i & 31;
        s_cat[i] = cat_emb[(long)cats[b * NCAT + c] * EDIM + e];
    }
    __syncthreads();

    if (t < ADIM) {
        float acc = 0.f;
        #pragma unroll
        for (int e = 0; e < EDIM; e++) acc += s_tgt[e] * Wq[e * ADIM + t];
        s_q[t] = acc;
    }
    __syncthreads();

    if (t < EDIM) {
        float acc = 0.f;
        for (int a = 0; a < ADIM; a++) acc += Wk[t * ADIM + a] * s_q[a];
        s_qk[t] = acc;
    }
    __syncthreads();

    const float scale = rsqrtf((float)ADIM);
    const int sub = lane & 7;
    const int tg  = lane >> 3;
    const float4 qv4 = *(const float4*)&s_qk[sub * 4];
    const int* srow = seqs + (long)b * SEQL;
    for (int p = warp * 128; p < warp * 128 + 128; p += 16) {
        int tokA = srow[p + tg];
        int tokB = srow[p + 4 + tg];
        int tokC = srow[p + 8 + tg];
        int tokD = srow[p + 12 + tg];
        float4 ea = *(const float4*)(seq_emb + (long)tokA * EDIM + sub * 4);
        float4 eb = *(const float4*)(seq_emb + (long)tokB * EDIM + sub * 4);
        float4 ec = *(const float4*)(seq_emb + (long)tokC * EDIM + sub * 4);
        float4 ed = *(const float4*)(seq_emb + (long)tokD * EDIM + sub * 4);
        float va = ea.x * qv4.x + ea.y * qv4.y + ea.z * qv4.z + ea.w * qv4.w;
        float vb = eb.x * qv4.x + eb.y * qv4.y + eb.z * qv4.z + eb.w * qv4.w;
        float vc = ec.x * qv4.x + ec.y * qv4.y + ec.z * qv4.z + ec.w * qv4.w;
        float vd = ed.x * qv4.x + ed.y * qv4.y + ed.z * qv4.z + ed.w * qv4.w;
        #pragma unroll
        for (int o = 4; o > 0; o >>= 1) {
            va += __shfl_xor_sync(0xffffffffu, va, o);
            vb += __shfl_xor_sync(0xffffffffu, vb, o);
            vc += __shfl_xor_sync(0xffffffffu, vc, o);
            vd += __shfl_xor_sync(0xffffffffu, vd, o);
        }
        if (sub == 0) {
            s_scores[p + tg]      = va * scale;
            s_scores[p + 4 + tg]  = vb * scale;
            s_scores[p + 8 + tg]  = vc * scale;
            s_scores[p + 12 + tg] = vd * scale;
        }
    }
    __syncthreads();

    if (warp == 0) {
        float sc[32];
        #pragma unroll
        for (int r = 0; r < 32; r++) sc[r] = s_scores[r * 32 + lane];

        float myval = -CUDART_INF_F;
        int   myidx = 0;

        for (int k = 0; k < TOPK; k++) {
            float bv = sc[0]; int br = 0;
            #pragma unroll
            for (int r = 1; r < 32; r++)
                if (sc[r] > bv) { bv = sc[r]; br = r; }
            int bi = br * 32 + lane;
            #pragma unroll
            for (int o = 16; o > 0; o >>= 1) {
                float ov = __shfl_xor_sync(0xffffffffu, bv, o);
                int   oi = __shfl_xor_sync(0xffffffffu, bi, o);
                if (ov > bv || (ov == bv && oi < bi)) { bv = ov; bi = oi; }
            }
            if (lane == k) { myval = bv; myidx = bi; }
            const int kr = bi >> 5;
            const int kl = bi & 31;
            #pragma unroll
            for (int r = 0; r < 32; r++)
                sc[r] = (r == kr && lane == kl) ? -CUDART_INF_F : sc[r];
        }

        float m = myval;
        #pragma unroll
        for (int o = 16; o > 0; o >>= 1) m = fmaxf(m, __shfl_xor_sync(0xffffffffu, m, o));
        float ev = (lane < TOPK) ? expf(myval - m) : 0.f;
        float s = ev;
        #pragma unroll
        for (int o = 16; o > 0; o >>= 1) s += __shfl_xor_sync(0xffffffffu, s, o);
        if (lane < TOPK) {
            s_topw[lane]   = ev / s;
            s_toptok[lane] = srow[myidx];
        }
    }
    __syncthreads();

    if (t < EDIM) {
        float acc = 0.f;
        #pragma unroll
        for (int k = 0; k < TOPK; k++)
            acc += s_topw[k] * seq_emb[(long)s_toptok[k] * EDIM + t];
        s_ctx[t] = acc;
    }
    __syncthreads();

    if (t < ADIM) {
        float acc = 0.f;
        #pragma unroll
        for (int e = 0; e < EDIM; e++) acc += s_ctx[e] * Wv[e * ADIM + t];
        s_tmp[t] = acc;
    }
    {
        float cp = 0.f;
        const int j = lane;
        const int i0 = warp * 80;
        for (int i = i0; i < i0 + 80; i++)
            cp += s_cat[i] * Wpool[i * EDIM + j];
        s_red[t] = cp;
    }
    __syncthreads();

    if (t < EDIM) {
        float inter = bo[t];
        for (int a = 0; a < ADIM; a++) inter += s_tmp[a] * Wo[a * EDIM + t];
        float cp = bpool[t];
        #pragma unroll
        for (int p = 0; p < 8; p++) cp += s_red[p * 32 + t];
        float ne = bnum[t];
        #pragma unroll
        for (int i = 0; i < NNUM; i++) ne += nums[b * NNUM + i] * Wnum[i * EDIM + t];

        float* fo = g_fused + (long)b * 128;
        fo[t]      = s_tgt[t];
        fo[32 + t] = inter;
        fo[64 + t] = cp;
        fo[96 + t] = ne;
    }
}

// ---------------------------------------------------------------------------
// Phase 2 v2: 1024 threads/CTA (32 warps), split-i partial sums + smem reduce.
// thread = (j = t&255, quarter q = t>>8). 8 rows per CTA, grid = 128.
// Fixes R9 finding: occ 12.4% / issue 14.7% — latency-bound at 8 warps/SM.
// ---------------------------------------------------------------------------
__global__ void __launch_bounds__(1024, 1) k_mlp(
    const float* __restrict__ Wmlp, const float* __restrict__ bmlp,
    const float* __restrict__ W1a, const float* __restrict__ b1a,
    const float* __restrict__ W2a, const float* __restrict__ b2a,
    const float* __restrict__ Wpa, const float* __restrict__ bpa,
    const float* __restrict__ W1b, const float* __restrict__ b1b,
    const float* __restrict__ W2b, const float* __restrict__ b2b,
    const float* __restrict__ Wpb, const float* __restrict__ bpb,
    const float* __restrict__ Wout, const float* __restrict__ bout,
    float* __restrict__ out)
{
    __shared__ float s_h[ROWS][HDIM];            // 8 KB
    __shared__ float s_qd[ROWS][HDIM];           // 8 KB (aliased as s_f early)
    __shared__ float s_p[4][ROWS][HDIM];         // 32 KB partials

    const int t  = threadIdx.x;
    const int j  = t & 255;       // output dim
    const int q  = t >> 8;        // i-quarter
    const int b0 = blockIdx.x * ROWS;

    // load fused [8][128] into aliased region of s_qd
    float* s_f = (float*)s_qd;    // [ROWS][128] = 4 KB of the 8 KB
    for (int i = t; i < ROWS * 128; i += 1024)
        s_f[i] = g_fused[(long)b0 * 128 + i];
    __syncthreads();

    // ---- stage 1: h = relu(fused @ Wmlp + bmlp). i-range 128, 32 per quarter.
    {
        float acc[ROWS];
        #pragma unroll
        for (int r = 0; r < ROWS; r++) acc[r] = 0.f;
        const int i0 = q * 32;
        for (int i = i0; i < i0 + 32; i += 4) {
            float w0 = Wmlp[(i + 0) * HDIM + j];
            float w1 = Wmlp[(i + 1) * HDIM + j];
            float w2 = Wmlp[(i + 2) * HDIM + j];
            float w3 = Wmlp[(i + 3) * HDIM + j];
            #pragma unroll
            for (int r = 0; r < ROWS; r++) {
                const float4 f4 = *(const float4*)&s_f[r * 128 + i];
                acc[r] += f4.x * w0 + f4.y * w1 + f4.z * w2 + f4.w * w3;
            }
        }
        #pragma unroll
        for (int r = 0; r < ROWS; r++) s_p[q][r][j] = acc[r];
    }
    __syncthreads();
    {   // reduce 4 quarters; each thread owns rows q*2, q*2+1. Writes s_h
        // (distinct from s_f alias, which is dead after this point).
        const float bm = bmlp[j];
        #pragma unroll
        for (int rr = 0; rr < 2; rr++) {
            const int r = q * 2 + rr;
            float v = bm + s_p[0][r][j] + s_p[1][r][j] + s_p[2][r][j] + s_p[3][r][j];
            s_h[r][j] = fmaxf(v, 0.f);
        }
    }
    __syncthreads();

    // ---- two QNN blocks
    #pragma unroll 1
    for (int blk = 0; blk < 2; blk++) {
        const float* W1 = blk ? W1b : W1a;
        const float* B1 = blk ? b1b : b1a;
        const float* W2 = blk ? W2b : W2a;
        const float* B2 = blk ? b2b : b2a;
        const float* Wp = blk ? Wpb : Wpa;
        const float* Bp = blk ? bpb : bpa;
        const int i0 = q * 64;

        // t1 partials
        {
            float acc[ROWS];
            #pragma unroll
            for (int r = 0; r < ROWS; r++) acc[r] = 0.f;
            for (int i = i0; i < i0 + 64; i += 4) {
                float w0 = W1[(i + 0) * HDIM + j];
                float w1 = W1[(i + 1) * HDIM + j];
                float w2 = W1[(i + 2) * HDIM + j];
                float w3 = W1[(i + 3) * HDIM + j];
                #pragma unroll
                for (int r = 0; r < ROWS; r++) {
                    const float4 h4 = *(const float4*)&s_h[r][i];
                    acc[r] += h4.x * w0 + h4.y * w1 + h4.z * w2 + h4.w * w3;
                }
            }
            #pragma unroll
            for (int r = 0; r < ROWS; r++) s_p[q][r][j] = acc[r];
        }
        __syncthreads();
        {   // reduce t1 -> stash in s_qd
            const float bb1 = B1[j];
            #pragma unroll
            for (int rr = 0; rr < 2; rr++) {
                const int r = q * 2 + rr;
                s_qd[r][j] = bb1 + s_p[0][r][j] + s_p[1][r][j] + s_p[2][r][j] + s_p[3][r][j];
            }
        }
        __syncthreads();

        // t2 partials (reuse s_p)
        {
            float acc[ROWS];
            #pragma unroll
            for (int r = 0; r < ROWS; r++) acc[r] = 0.f;
            for (int i = i0; i < i0 + 64; i += 4) {
                float w0 = W2[(i + 0) * HDIM + j];
                float w1 = W2[(i + 1) * HDIM + j];
                float w2 = W2[(i + 2) * HDIM + j];
                float w3 = W2[(i + 3) * HDIM + j];
                #pragma unroll
                for (int r = 0; r < ROWS; r++) {
                    const float4 h4 = *(const float4*)&s_h[r][i];
                    acc[r] += h4.x * w0 + h4.y * w1 + h4.z * w2 + h4.w * w3;
                }
            }
            #pragma unroll
            for (int r = 0; r < ROWS; r++) s_p[q][r][j] = acc[r];
        }
        __syncthreads();
        {   // reduce t2, qd = t1 * t2
            const float bb2 = B2[j];
            #pragma unroll
            for (int rr = 0; rr < 2; rr++) {
                const int r = q * 2 + rr;
                float t2v = bb2 + s_p[0][r][j] + s_p[1][r][j] + s_p[2][r][j] + s_p[3][r][j];
                s_qd[r][j] = s_qd[r][j] * t2v;
            }
        }
        __syncthreads();

        // projection partials over qd
        {
            float acc[ROWS];
            #pragma unroll
            for (int r = 0; r < ROWS; r++) acc[r] = 0.f;
            for (int i = i0; i < i0 + 64; i += 4) {
                float w0 = Wp[(i + 0) * HDIM + j];
                float w1 = Wp[(i + 1) * HDIM + j];
                float w2 = Wp[(i + 2) * HDIM + j];
                float w3 = Wp[(i + 3) * HDIM + j];
                #pragma unroll
                for (int r = 0; r < ROWS; r++) {
                    const float4 q4 = *(const float4*)&s_qd[r][i];
                    acc[r] += q4.x * w0 + q4.y * w1 + q4.z * w2 + q4.w * w3;
                }
            }
            #pragma unroll
            for (int r = 0; r < ROWS; r++) s_p[q][r][j] = acc[r];
        }
        __syncthreads();
        {   // reduce + residual into s_h
            const float bp_ = Bp[j];
            #pragma unroll
            for (int rr = 0; rr < 2; rr++) {
                const int r = q * 2 + rr;
                s_h[r][j] += bp_ + s_p[0][r][j] + s_p[1][r][j] + s_p[2][r][j] + s_p[3][r][j];
            }
        }
        __syncthreads();
    }

    // ---- head: out[b] = h . Wout + bout. 4 warps per row, 64 j each.
    {
        const int w    = t >> 5;
        const int lane = t & 31;
        const int r    = w >> 2;          // row 0..7
        const int jb   = (w & 3) * 64;    // j segment
        float sum = s_h[r][jb + lane]      * Wout[jb + lane]
                  + s_h[r][jb + 32 + lane] * Wout[jb + 32 + lane];
        #pragma unroll
        for (int o = 16; o > 0; o >>= 1)
            sum += __shfl_xor_sync(0xffffffffu, sum, o);
        float* s_hd = (float*)s_p;        // 32 partials
        if (lane == 0) s_hd[w] = sum;
        __syncthreads();
        if (t < ROWS)
            out[b0 + t] = bout[0] + s_hd[t * 4] + s_hd[t * 4 + 1]
                        + s_hd[t * 4 + 2] + s_hd[t * 4 + 3];
    }
}

extern "C" void kernel_launch(void* const* d_in, const int* in_sizes, int n_in,
                              void* d_out, int out_size)
{
    const int*   cats    = (const int*)d_in[0];
    const float* nums    = (const float*)d_in[1];
    const int*   seqs    = (const int*)d_in[2];
    const int*   tgt_ids = (const int*)d_in[3];
    const float* cat_emb = (const float*)d_in[4];
    const float* seq_emb = (const float*)d_in[5];
    const float* Wnum    = (const float*)d_in[6];
    const float* bnum    = (const float*)d_in[7];
    const float* Wq      = (const float*)d_in[8];
    const float* Wk      = (const float*)d_in[9];
    const float* Wv      = (const float*)d_in[10];
    const float* Wo      = (const float*)d_in[11];
    const float* bo      = (const float*)d_in[12];
    const float* Wpool   = (const float*)d_in[13];
    const float* bpool   = (const float*)d_in[14];
    const float* Wmlp    = (const float*)d_in[15];
    const float* bmlp    = (const float*)d_in[16];
    const float* q1_W1   = (const float*)d_in[17];
    const float* q1_b1   = (const float*)d_in[18];
    const float* q1_W2   = (const float*)d_in[19];
    const float* q1_b2   = (const float*)d_in[20];
    const float* q1_Wp   = (const float*)d_in[21];
    const float* q1_bp   = (const float*)d_in[22];
    const float* q2_W1   = (const float*)d_in[23];
    const float* q2_b1   = (const float*)d_in[24];
    const float* q2_W2   = (const float*)d_in[25];
    const float* q2_b2   = (const float*)d_in[26];
    const float* q2_Wp   = (const float*)d_in[27];
    const float* q2_bp   = (const float*)d_in[28];
    const float* Wout    = (const float*)d_in[29];
    const float* bout    = (const float*)d_in[30];
    float* out = (float*)d_out;

    k_attn<<<BATCH, 256>>>(cats, nums, seqs, tgt_ids, cat_emb, seq_emb,
                           Wnum, bnum, Wq, Wk, Wv, Wo, bo, Wpool, bpool);
    k_mlp<<<BATCH / ROWS, 1024>>>(Wmlp, bmlp,
                                  q1_W1, q1_b1, q1_W2, q1_b2, q1_Wp, q1_bp,
                                  q2_W1, q2_b1, q2_W2, q2_b2, q2_Wp, q2_bp,
                                  Wout, bout, out);
}